// round 3
// baseline (speedup 1.0000x reference)
#include <cuda_runtime.h>
#include <math.h>

#define LL   16384
#define KTL  4096
#define NB   32
#define NT   50
#define NTH  512
#define TWN  4096   /* LL/4 twiddle table entries */

// ---------------- device scratch (static allocations only) ----------------
__device__ float2 g_S[2][LL];      // spectra of whitening filters (digit-reversed order)
__device__ float2 g_H[100][LL];    // spectra of templates [n*2+c]
__device__ float2 g_D[64][LL];     // Xi spectrum * conj(S)  [b*2+c]
__device__ float  g_z[NB * 2 * NT];
__device__ float2 g_tw[TWN];       // w^k = exp(-2*pi*i*k/LL), k < LL/4

// ---------------- complex helpers ----------------
__device__ __forceinline__ float2 cadd(float2 a, float2 b) { return make_float2(a.x + b.x, a.y + b.y); }
__device__ __forceinline__ float2 csub(float2 a, float2 b) { return make_float2(a.x - b.x, a.y - b.y); }
__device__ __forceinline__ float2 cmul(float2 a, float2 b) {
    return make_float2(a.x * b.x - a.y * b.y, a.x * b.y + a.y * b.x);
}
__device__ __forceinline__ float2 cmulcj(float2 a, float2 b) {  // a * conj(b)
    return make_float2(a.x * b.x + a.y * b.y, a.y * b.x - a.x * b.y);
}

// ---------------- twiddle table (double-precision generation) ----------------
__global__ void k_twiddle() {
    int k = blockIdx.x * blockDim.x + threadIdx.x;
    if (k < TWN) {
        double a = -2.0 * 3.14159265358979323846 * (double)k / (double)LL;
        double s, c;
        sincos(a, &s, &c);
        g_tw[k] = make_float2((float)c, (float)s);
    }
}

// ---------------- in-place radix-4 FFT over smem, 16384 points ----------------
// Forward: DIF, natural input -> base-4 digit-reversed output, w = exp(-2*pi*i/N).
// Inverse: DIT (stages reversed), digit-reversed input -> natural output, conj
// twiddles, unscaled (caller divides by N).
// Only one twiddle is loaded per butterfly; w^2, w^3 are computed in registers.
template <bool INV>
__device__ void fft16k(float2* __restrict__ s, const float2* __restrict__ tw) {
    const int tid = threadIdx.x;
#pragma unroll 1
    for (int si = 0; si < 7; si++) {
        const int st   = INV ? (6 - si) : si;
        const int logm = 12 - 2 * st;
        const int m    = 1 << logm;
#pragma unroll
        for (int it = 0; it < (LL / 4) / NTH; it++) {
            const int bf   = tid + it * NTH;
            const int j    = bf & (m - 1);
            const int base = ((bf >> logm) << (logm + 2)) + j;

            float2 a0 = s[base];
            float2 a1 = s[base + m];
            float2 a2 = s[base + 2 * m];
            float2 a3 = s[base + 3 * m];
            float2 w1 = tw[j << (2 * st)];

            if (INV) {
                w1.y = -w1.y;  // conjugate for inverse
                float2 w2 = make_float2(w1.x * w1.x - w1.y * w1.y, 2.f * w1.x * w1.y);
                float2 w3 = cmul(w2, w1);
                a1 = cmul(a1, w1);
                a2 = cmul(a2, w2);
                a3 = cmul(a3, w3);
                float2 p02 = cadd(a0, a2), m02 = csub(a0, a2);
                float2 p13 = cadd(a1, a3), m13 = csub(a1, a3);
                float2 i13 = make_float2(-m13.y, m13.x);  // +i*(a1-a3)
                s[base]         = cadd(p02, p13);
                s[base + m]     = cadd(m02, i13);
                s[base + 2 * m] = csub(p02, p13);
                s[base + 3 * m] = csub(m02, i13);
            } else {
                float2 p02 = cadd(a0, a2), m02 = csub(a0, a2);
                float2 p13 = cadd(a1, a3), m13 = csub(a1, a3);
                float2 ni13 = make_float2(m13.y, -m13.x);  // -i*(a1-a3)
                float2 b0 = cadd(p02, p13);
                float2 b1 = cadd(m02, ni13);
                float2 b2 = csub(p02, p13);
                float2 b3 = csub(m02, ni13);
                float2 w2 = make_float2(w1.x * w1.x - w1.y * w1.y, 2.f * w1.x * w1.y);
                float2 w3 = cmul(w2, w1);
                s[base]         = b0;
                s[base + m]     = cmul(b1, w1);
                s[base + 2 * m] = cmul(b2, w2);
                s[base + 3 * m] = cmul(b3, w3);
            }
        }
        __syncthreads();
    }
}

// ---------------- forward FFT of S (2 blocks) + templates (100 blocks) ----------------
__global__ void __launch_bounds__(NTH, 1) k_fft_in(const float* __restrict__ Sm,
                                                   const float* __restrict__ Tm) {
    extern __shared__ float2 sm[];
    float2* dat = sm;
    float2* tw  = sm + LL;
    const int tid = threadIdx.x;
    const int bi  = blockIdx.x;
    for (int k = tid; k < TWN; k += NTH) tw[k] = g_tw[k];
    if (bi < 2) {
        const float* src = Sm + bi * LL;
        for (int t = tid; t < LL; t += NTH) dat[t] = make_float2(src[t], 0.f);
    } else {
        const float* src = Tm + (size_t)(bi - 2) * KTL;  // template[n*2+c] row
        for (int t = tid; t < LL; t += NTH)
            dat[t] = make_float2(t < KTL ? src[t] : 0.f, 0.f);
    }
    __syncthreads();
    fft16k<false>(dat, tw);
    if (bi < 2) {
        for (int k = tid; k < LL; k += NTH) g_S[bi][k] = dat[k];
    } else {
        for (int k = tid; k < LL; k += NTH) g_H[bi - 2][k] = dat[k];
    }
}

// ---------------- forward FFT of xi (64 blocks), fused D = Xi * conj(S) ----------------
__global__ void __launch_bounds__(NTH, 1) k_fft_xi(const float* __restrict__ xi) {
    extern __shared__ float2 sm[];
    float2* dat = sm;
    float2* tw  = sm + LL;
    const int tid = threadIdx.x;
    const int bi  = blockIdx.x;  // = b*2 + c
    const int c   = bi & 1;
    for (int k = tid; k < TWN; k += NTH) tw[k] = g_tw[k];
    const float* src = xi + (size_t)bi * LL;
    for (int t = tid; t < LL; t += NTH) dat[t] = make_float2(src[t], 0.f);
    __syncthreads();
    fft16k<false>(dat, tw);
    for (int k = tid; k < LL; k += NTH)
        g_D[bi][k] = cmulcj(dat[k], g_S[c][k]);
}

// ---------------- inverse kernel: one block per (b,n); both channels packed ----------------
__global__ void __launch_bounds__(NTH, 1) k_inv(const float* __restrict__ hh) {
    extern __shared__ float2 sm[];
    float2* dat = sm;
    float2* tw  = sm + LL;
    const int tid = threadIdx.x;
    const int n = blockIdx.x;
    const int b = blockIdx.y;
    for (int k = tid; k < TWN; k += NTH) tw[k] = g_tw[k];
    const float2* __restrict__ D0 = g_D[b * 2 + 0];
    const float2* __restrict__ D1 = g_D[b * 2 + 1];
    const float2* __restrict__ H0 = g_H[n * 2 + 0];
    const float2* __restrict__ H1 = g_H[n * 2 + 1];
    for (int k = tid; k < LL; k += NTH) {
        float2 GA = cmulcj(D0[k], H0[k]);   // spectrum of corrA (conj-symmetric)
        float2 GE = cmulcj(D1[k], H1[k]);   // spectrum of corrE
        dat[k] = make_float2(GA.x - GE.y, GA.y + GE.x);  // GA + i*GE
    }
    __syncthreads();
    fft16k<true>(dat, tw);   // out: corrA + i*corrE (natural order, unscaled)

    float mA = -3.4e38f, mE = -3.4e38f;
    for (int k = tid; k < LL; k += NTH) {
        float2 v = dat[k];
        mA = fmaxf(mA, v.x);
        mE = fmaxf(mE, v.y);
    }
#pragma unroll
    for (int o = 16; o > 0; o >>= 1) {
        mA = fmaxf(mA, __shfl_xor_sync(0xffffffffu, mA, o));
        mE = fmaxf(mE, __shfl_xor_sync(0xffffffffu, mE, o));
    }
    __shared__ float rA[NTH / 32], rE[NTH / 32];
    if ((tid & 31) == 0) { rA[tid >> 5] = mA; rE[tid >> 5] = mE; }
    __syncthreads();
    if (tid == 0) {
        for (int i = 1; i < NTH / 32; i++) { mA = fmaxf(mA, rA[i]); mE = fmaxf(mE, rE[i]); }
        const float sc = 1.f / (float)LL;
        g_z[(b * 2 + 0) * NT + n] = mA * sc / hh[n * 2 + 0];
        g_z[(b * 2 + 1) * NT + n] = mE * sc / hh[n * 2 + 1];
    }
}

// ---------------- tiny CNN + MLP head: one block per batch ----------------
__device__ __forceinline__ float sigm(float x) { return 1.f / (1.f + __expf(-x)); }

__global__ void k_head(const float* __restrict__ W1, const float* __restrict__ b1,
                       const float* __restrict__ W2, const float* __restrict__ b2,
                       const float* __restrict__ W3, const float* __restrict__ b3,
                       const float* __restrict__ W4, const float* __restrict__ b4,
                       float* __restrict__ out) {
    __shared__ float zb[2][NT];
    __shared__ float p1[16][16];
    __shared__ float p2[32][4];
    __shared__ float h1[32];
    const int b = blockIdx.x, tid = threadIdx.x;
    for (int i = tid; i < 2 * NT; i += blockDim.x) zb[i / NT][i % NT] = g_z[b * 2 * NT + i];
    __syncthreads();
    // conv1 [16,2,3] + sigmoid + maxpool3 -> p1[16][16]
    for (int i = tid; i < 16 * 16; i += blockDim.x) {
        int o = i >> 4, tp = i & 15;
        float mx = -3.4e38f;
        for (int q = 0; q < 3; q++) {
            int t = 3 * tp + q;
            float acc = b1[o];
            for (int c = 0; c < 2; c++)
                for (int j = 0; j < 3; j++) acc += zb[c][t + j] * W1[(o * 2 + c) * 3 + j];
            mx = fmaxf(mx, sigm(acc));
        }
        p1[o][tp] = mx;
    }
    __syncthreads();
    // conv2 [32,16,3] + sigmoid + maxpool3 (floor: 14 -> 4) -> p2[32][4]
    for (int i = tid; i < 32 * 4; i += blockDim.x) {
        int o = i >> 2, tp = i & 3;
        float mx = -3.4e38f;
        for (int q = 0; q < 3; q++) {
            int t = 3 * tp + q;
            float acc = b2[o];
            for (int ci = 0; ci < 16; ci++)
                for (int j = 0; j < 3; j++) acc += p1[ci][t + j] * W2[(o * 16 + ci) * 3 + j];
            mx = fmaxf(mx, sigm(acc));
        }
        p2[o][tp] = mx;
    }
    __syncthreads();
    if (tid < 32) {
        float acc = b3[tid];
        for (int i = 0; i < 128; i++) acc += p2[i >> 2][i & 3] * W3[tid * 128 + i];
        h1[tid] = fmaxf(acc, 0.f);
    }
    __syncthreads();
    if (tid < 2) {
        float acc = b4[tid];
        for (int i = 0; i < 32; i++) acc += h1[i] * W4[tid * 32 + i];
        out[b * 2 + tid] = acc;
    }
}

// ---------------- launch ----------------
extern "C" void kernel_launch(void* const* d_in, const int* in_sizes, int n_in,
                              void* d_out, int out_size) {
    const float* xi = (const float*)d_in[0];
    const float* S  = (const float*)d_in[1];
    const float* Tm = (const float*)d_in[2];
    const float* hh = (const float*)d_in[3];
    const float* W1 = (const float*)d_in[4];
    const float* b1 = (const float*)d_in[5];
    const float* W2 = (const float*)d_in[6];
    const float* b2 = (const float*)d_in[7];
    const float* W3 = (const float*)d_in[8];
    const float* b3 = (const float*)d_in[9];
    const float* W4 = (const float*)d_in[10];
    const float* b4 = (const float*)d_in[11];

    const size_t shb = (size_t)(LL + TWN) * sizeof(float2);  // 160 KB
    cudaFuncSetAttribute(k_fft_in, cudaFuncAttributeMaxDynamicSharedMemorySize, (int)shb);
    cudaFuncSetAttribute(k_fft_xi, cudaFuncAttributeMaxDynamicSharedMemorySize, (int)shb);
    cudaFuncSetAttribute(k_inv,    cudaFuncAttributeMaxDynamicSharedMemorySize, (int)shb);

    k_twiddle<<<(TWN + 255) / 256, 256>>>();
    k_fft_in<<<102, NTH, shb>>>(S, Tm);
    k_fft_xi<<<64, NTH, shb>>>(xi);
    dim3 gi(NT, NB);
    k_inv<<<gi, NTH, shb>>>(hh);
    k_head<<<NB, 128>>>(W1, b1, W2, b2, W3, b3, W4, b4, (float*)d_out);
}

// round 4
// speedup vs baseline: 2.0325x; 2.0325x over previous
#include <cuda_runtime.h>
#include <math.h>

#define LL   16384
#define KTL  4096
#define NB   32
#define NT   50
#define NTH  512

// compact per-stage twiddle tables, flat layout
#define TWF   5461
#define O4096 0
#define O1024 4096
#define O256  5120
#define O64   5376
#define O16   5440
#define O4    5456
#define O1    5460

// ---------------- device scratch ----------------
__device__ float2 g_S[2][LL];
__device__ float2 g_H[100][LL];
__device__ float2 g_D[64][LL];
__device__ float  g_z[NB * 2 * NT];
__device__ float2 g_twf[TWF];

// smem bank swizzle: pure permutation, applied to ALL workspace accesses
#define SW(k) ((k) ^ (((k) >> 4) & 15))

// ---------------- complex helpers ----------------
__device__ __forceinline__ float2 cadd(float2 a, float2 b) { return make_float2(a.x + b.x, a.y + b.y); }
__device__ __forceinline__ float2 csub(float2 a, float2 b) { return make_float2(a.x - b.x, a.y - b.y); }
__device__ __forceinline__ float2 cmul(float2 a, float2 b) {
    return make_float2(a.x * b.x - a.y * b.y, a.x * b.y + a.y * b.x);
}
__device__ __forceinline__ float2 cmulcj(float2 a, float2 b) {  // a * conj(b)
    return make_float2(a.x * b.x + a.y * b.y, a.y * b.x - a.x * b.y);
}

// forward DIF radix-4: butterfly then twiddle outputs (w = exp(-2pi i /4m))
__device__ __forceinline__ void bf_fwd(float2& x0, float2& x1, float2& x2, float2& x3, float2 w1) {
    float2 p02 = cadd(x0, x2), m02 = csub(x0, x2);
    float2 p13 = cadd(x1, x3), m13 = csub(x1, x3);
    float2 ni  = make_float2(m13.y, -m13.x);      // -i*(x1-x3)
    float2 b0 = cadd(p02, p13), b1 = cadd(m02, ni);
    float2 b2 = csub(p02, p13), b3 = csub(m02, ni);
    float2 w2 = make_float2(w1.x * w1.x - w1.y * w1.y, 2.f * w1.x * w1.y);
    float2 w3 = cmul(w2, w1);
    x0 = b0; x1 = cmul(b1, w1); x2 = cmul(b2, w2); x3 = cmul(b3, w3);
}

// inverse DIT radix-4: conj-twiddle inputs then butterfly
__device__ __forceinline__ void bf_inv(float2& x0, float2& x1, float2& x2, float2& x3, float2 w1) {
    w1.y = -w1.y;
    float2 w2 = make_float2(w1.x * w1.x - w1.y * w1.y, 2.f * w1.x * w1.y);
    float2 w3 = cmul(w2, w1);
    float2 a1 = cmul(x1, w1), a2 = cmul(x2, w2), a3 = cmul(x3, w3);
    float2 p02 = cadd(x0, a2), m02 = csub(x0, a2);
    float2 p13 = cadd(a1, a3), m13 = csub(a1, a3);
    float2 pi  = make_float2(-m13.y, m13.x);      // +i*(a1-a3)
    x0 = cadd(p02, p13); x1 = cadd(m02, pi);
    x2 = csub(p02, p13); x3 = csub(m02, pi);
}

// ---------------- twiddle generation (double precision) ----------------
__global__ void k_twiddle() {
    int i = blockIdx.x * blockDim.x + threadIdx.x;
    if (i >= TWF) return;
    int m, j;
    if      (i < O1024) { m = 4096; j = i; }
    else if (i < O256)  { m = 1024; j = i - O1024; }
    else if (i < O64)   { m = 256;  j = i - O256; }
    else if (i < O16)   { m = 64;   j = i - O64; }
    else if (i < O4)    { m = 16;   j = i - O16; }
    else if (i < O1)    { m = 4;    j = i - O4; }
    else                { m = 1;    j = 0; }
    double a = -2.0 * 3.14159265358979323846 * (double)j / (4.0 * (double)m);
    double s, c; sincos(a, &s, &c);
    g_twf[i] = make_float2((float)c, (float)s);
}

__device__ __forceinline__ void loadtw(float2* tw) {
    for (int k = threadIdx.x; k < TWF; k += NTH) tw[k] = g_twf[k];
}

// ---------------- combined radix-16 pass (two radix-4 stages in registers) ----------------
// Tile: elements base + q*MS, q = q0 + 4*q1. Small stage (stride MS) over q0,
// big stage (stride 4*MS) over q1. Forward runs big->small, inverse small->big.
template <int MS, bool FWD>
__device__ void pass16(float2* __restrict__ s, const float2* __restrict__ Ts,
                       const float2* __restrict__ Tb) {
    const int tid = threadIdx.x;
#pragma unroll 1
    for (int i = 0; i < 2; i++) {
        const int tau  = tid + i * NTH;
        const int j    = tau & (MS - 1);
        const int g    = tau / MS;
        const int base = g * (16 * MS) + j;
        float2 x[16];
#pragma unroll
        for (int q = 0; q < 16; q++) x[q] = s[SW(base + q * MS)];
        if (FWD) {
#pragma unroll
            for (int q0 = 0; q0 < 4; q0++) {
                float2 wb = Tb[j + q0 * MS];
                bf_fwd(x[q0], x[q0 + 4], x[q0 + 8], x[q0 + 12], wb);
            }
            float2 ws = Ts[j];
#pragma unroll
            for (int q1 = 0; q1 < 4; q1++)
                bf_fwd(x[4 * q1], x[4 * q1 + 1], x[4 * q1 + 2], x[4 * q1 + 3], ws);
        } else {
            float2 ws = Ts[j];
#pragma unroll
            for (int q1 = 0; q1 < 4; q1++)
                bf_inv(x[4 * q1], x[4 * q1 + 1], x[4 * q1 + 2], x[4 * q1 + 3], ws);
#pragma unroll
            for (int q0 = 0; q0 < 4; q0++) {
                float2 wb = Tb[j + q0 * MS];
                bf_inv(x[q0], x[q0 + 4], x[q0 + 8], x[q0 + 12], wb);
            }
        }
#pragma unroll
        for (int q = 0; q < 16; q++) s[SW(base + q * MS)] = x[q];
    }
    __syncthreads();
}

// forward stages (4096,1024),(256,64),(16,4); final m=1 is fused by callers
__device__ __forceinline__ void fwd_core(float2* dat, const float2* tw) {
    pass16<1024, true>(dat, tw + O1024, tw + O4096);
    pass16<64,   true>(dat, tw + O64,   tw + O256);
    pass16<4,    true>(dat, tw + O4,    tw + O16);
}

// final forward m=1 butterfly (twiddle = 1), inputs from swizzled smem
__device__ __forceinline__ void last_fwd(const float2* dat, int k0, float2& b0, float2& b1,
                                         float2& b2, float2& b3) {
    float2 x0 = dat[SW(k0)], x1 = dat[SW(k0 + 1)], x2 = dat[SW(k0 + 2)], x3 = dat[SW(k0 + 3)];
    float2 p02 = cadd(x0, x2), m02 = csub(x0, x2);
    float2 p13 = cadd(x1, x3), m13 = csub(x1, x3);
    float2 ni  = make_float2(m13.y, -m13.x);
    b0 = cadd(p02, p13); b1 = cadd(m02, ni);
    b2 = csub(p02, p13); b3 = csub(m02, ni);
}

// ---------------- forward FFT of S (2) + templates (100) ----------------
__global__ void __launch_bounds__(NTH, 1) k_fft_in(const float* __restrict__ Sm,
                                                   const float* __restrict__ Tm) {
    extern __shared__ float2 sm[];
    float2* dat = sm;
    float2* tw  = sm + LL;
    const int tid = threadIdx.x, bi = blockIdx.x;
    loadtw(tw);
    if (bi < 2) {
        const float* src = Sm + bi * LL;
        for (int t = tid; t < LL; t += NTH) dat[SW(t)] = make_float2(src[t], 0.f);
    } else {
        const float* src = Tm + (size_t)(bi - 2) * KTL;
        for (int t = tid; t < LL; t += NTH)
            dat[SW(t)] = make_float2(t < KTL ? src[t] : 0.f, 0.f);
    }
    __syncthreads();
    fwd_core(dat, tw);
    float2* out = (bi < 2) ? g_S[bi] : g_H[bi - 2];
#pragma unroll 1
    for (int i = 0; i < 8; i++) {
        const int k0 = 4 * (tid + i * NTH);
        float2 b0, b1, b2, b3;
        last_fwd(dat, k0, b0, b1, b2, b3);
        float4* o4 = (float4*)(out + k0);
        o4[0] = make_float4(b0.x, b0.y, b1.x, b1.y);
        o4[1] = make_float4(b2.x, b2.y, b3.x, b3.y);
    }
}

// ---------------- forward FFT of xi (64), fused D = Xi * conj(S) ----------------
__global__ void __launch_bounds__(NTH, 1) k_fft_xi(const float* __restrict__ xi) {
    extern __shared__ float2 sm[];
    float2* dat = sm;
    float2* tw  = sm + LL;
    const int tid = threadIdx.x, bi = blockIdx.x;  // b*2 + c
    const int c   = bi & 1;
    loadtw(tw);
    const float* src = xi + (size_t)bi * LL;
    for (int t = tid; t < LL; t += NTH) dat[SW(t)] = make_float2(src[t], 0.f);
    __syncthreads();
    fwd_core(dat, tw);
    const float2* Sc = g_S[c];
    float2* Dd = g_D[bi];
#pragma unroll 1
    for (int i = 0; i < 8; i++) {
        const int k0 = 4 * (tid + i * NTH);
        float2 b0, b1, b2, b3;
        last_fwd(dat, k0, b0, b1, b2, b3);
        const float4* s4 = (const float4*)(Sc + k0);
        float4 sA = s4[0], sB = s4[1];
        float2 d0 = cmulcj(b0, make_float2(sA.x, sA.y));
        float2 d1 = cmulcj(b1, make_float2(sA.z, sA.w));
        float2 d2 = cmulcj(b2, make_float2(sB.x, sB.y));
        float2 d3 = cmulcj(b3, make_float2(sB.z, sB.w));
        float4* o4 = (float4*)(Dd + k0);
        o4[0] = make_float4(d0.x, d0.y, d1.x, d1.y);
        o4[1] = make_float4(d2.x, d2.y, d3.x, d3.y);
    }
}

// ---------------- inverse: pointwise+stage(m=1) -> (4,16) -> (64,256) -> (1024,4096)+max ----------------
__global__ void __launch_bounds__(NTH, 1) k_inv(const float* __restrict__ hh) {
    extern __shared__ float2 sm[];
    float2* dat = sm;
    float2* tw  = sm + LL;
    const int tid = threadIdx.x;
    const int n = blockIdx.x, b = blockIdx.y;
    loadtw(tw);
    const float2* __restrict__ D0 = g_D[b * 2 + 0];
    const float2* __restrict__ D1 = g_D[b * 2 + 1];
    const float2* __restrict__ H0 = g_H[n * 2 + 0];
    const float2* __restrict__ H1 = g_H[n * 2 + 1];
    // pointwise spectral product (pack channels: GA + i*GE) fused with first
    // inverse stage (m=1, twiddle=1); fully coalesced float4 global loads.
#pragma unroll 1
    for (int i = 0; i < 8; i++) {
        const int tau = tid + i * NTH;
        const int k0  = 4 * tau;
        const float4* d0p = (const float4*)(D0 + k0);
        const float4* d1p = (const float4*)(D1 + k0);
        const float4* h0p = (const float4*)(H0 + k0);
        const float4* h1p = (const float4*)(H1 + k0);
        float4 dA = d0p[0], dB = d0p[1], eA = d1p[0], eB = d1p[1];
        float4 hA = h0p[0], hB = h0p[1], fA = h1p[0], fB = h1p[1];
        float2 v[4];
        {
            float2 GA, GE;
            GA = cmulcj(make_float2(dA.x, dA.y), make_float2(hA.x, hA.y));
            GE = cmulcj(make_float2(eA.x, eA.y), make_float2(fA.x, fA.y));
            v[0] = make_float2(GA.x - GE.y, GA.y + GE.x);
            GA = cmulcj(make_float2(dA.z, dA.w), make_float2(hA.z, hA.w));
            GE = cmulcj(make_float2(eA.z, eA.w), make_float2(fA.z, fA.w));
            v[1] = make_float2(GA.x - GE.y, GA.y + GE.x);
            GA = cmulcj(make_float2(dB.x, dB.y), make_float2(hB.x, hB.y));
            GE = cmulcj(make_float2(eB.x, eB.y), make_float2(fB.x, fB.y));
            v[2] = make_float2(GA.x - GE.y, GA.y + GE.x);
            GA = cmulcj(make_float2(dB.z, dB.w), make_float2(hB.z, hB.w));
            GE = cmulcj(make_float2(eB.z, eB.w), make_float2(fB.z, fB.w));
            v[3] = make_float2(GA.x - GE.y, GA.y + GE.x);
        }
        // inverse radix-4, m=1, w=1
        float2 p02 = cadd(v[0], v[2]), m02 = csub(v[0], v[2]);
        float2 p13 = cadd(v[1], v[3]), m13 = csub(v[1], v[3]);
        float2 pi  = make_float2(-m13.y, m13.x);
        dat[SW(k0)]     = cadd(p02, p13);
        dat[SW(k0 + 1)] = cadd(m02, pi);
        dat[SW(k0 + 2)] = csub(p02, p13);
        dat[SW(k0 + 3)] = csub(m02, pi);
    }
    __syncthreads();
    pass16<4,  false>(dat, tw + O4,  tw + O16);
    pass16<64, false>(dat, tw + O64, tw + O256);
    // last combined pass (1024,4096): results stay in registers, fold max
    float mA = -3.4e38f, mE = -3.4e38f;
#pragma unroll 1
    for (int i = 0; i < 2; i++) {
        const int j = tid + i * NTH;  // g = 0 for all tiles here
        float2 x[16];
#pragma unroll
        for (int q = 0; q < 16; q++) x[q] = dat[SW(j + q * 1024)];
        float2 ws = tw[O1024 + j];
#pragma unroll
        for (int q1 = 0; q1 < 4; q1++)
            bf_inv(x[4 * q1], x[4 * q1 + 1], x[4 * q1 + 2], x[4 * q1 + 3], ws);
#pragma unroll
        for (int q0 = 0; q0 < 4; q0++) {
            float2 wb = tw[O4096 + j + q0 * 1024];
            bf_inv(x[q0], x[q0 + 4], x[q0 + 8], x[q0 + 12], wb);
        }
#pragma unroll
        for (int q = 0; q < 16; q++) {
            mA = fmaxf(mA, x[q].x);
            mE = fmaxf(mE, x[q].y);
        }
    }
#pragma unroll
    for (int o = 16; o > 0; o >>= 1) {
        mA = fmaxf(mA, __shfl_xor_sync(0xffffffffu, mA, o));
        mE = fmaxf(mE, __shfl_xor_sync(0xffffffffu, mE, o));
    }
    __shared__ float rA[NTH / 32], rE[NTH / 32];
    if ((tid & 31) == 0) { rA[tid >> 5] = mA; rE[tid >> 5] = mE; }
    __syncthreads();
    if (tid == 0) {
        for (int i = 1; i < NTH / 32; i++) { mA = fmaxf(mA, rA[i]); mE = fmaxf(mE, rE[i]); }
        const float sc = 1.f / (float)LL;
        g_z[(b * 2 + 0) * NT + n] = mA * sc / hh[n * 2 + 0];
        g_z[(b * 2 + 1) * NT + n] = mE * sc / hh[n * 2 + 1];
    }
}

// ---------------- tiny CNN + MLP head ----------------
__device__ __forceinline__ float sigm(float x) { return 1.f / (1.f + __expf(-x)); }

__global__ void k_head(const float* __restrict__ W1, const float* __restrict__ b1,
                       const float* __restrict__ W2, const float* __restrict__ b2,
                       const float* __restrict__ W3, const float* __restrict__ b3,
                       const float* __restrict__ W4, const float* __restrict__ b4,
                       float* __restrict__ out) {
    __shared__ float zb[2][NT];
    __shared__ float p1[16][16];
    __shared__ float p2[32][4];
    __shared__ float h1[32];
    const int b = blockIdx.x, tid = threadIdx.x;
    for (int i = tid; i < 2 * NT; i += blockDim.x) zb[i / NT][i % NT] = g_z[b * 2 * NT + i];
    __syncthreads();
    for (int i = tid; i < 16 * 16; i += blockDim.x) {
        int o = i >> 4, tp = i & 15;
        float mx = -3.4e38f;
        for (int q = 0; q < 3; q++) {
            int t = 3 * tp + q;
            float acc = b1[o];
            for (int c = 0; c < 2; c++)
                for (int j = 0; j < 3; j++) acc += zb[c][t + j] * W1[(o * 2 + c) * 3 + j];
            mx = fmaxf(mx, sigm(acc));
        }
        p1[o][tp] = mx;
    }
    __syncthreads();
    for (int i = tid; i < 32 * 4; i += blockDim.x) {
        int o = i >> 2, tp = i & 3;
        float mx = -3.4e38f;
        for (int q = 0; q < 3; q++) {
            int t = 3 * tp + q;
            float acc = b2[o];
            for (int ci = 0; ci < 16; ci++)
                for (int j = 0; j < 3; j++) acc += p1[ci][t + j] * W2[(o * 16 + ci) * 3 + j];
            mx = fmaxf(mx, sigm(acc));
        }
        p2[o][tp] = mx;
    }
    __syncthreads();
    if (tid < 32) {
        float acc = b3[tid];
        for (int i = 0; i < 128; i++) acc += p2[i >> 2][i & 3] * W3[tid * 128 + i];
        h1[tid] = fmaxf(acc, 0.f);
    }
    __syncthreads();
    if (tid < 2) {
        float acc = b4[tid];
        for (int i = 0; i < 32; i++) acc += h1[i] * W4[tid * 32 + i];
        out[b * 2 + tid] = acc;
    }
}

// ---------------- launch ----------------
extern "C" void kernel_launch(void* const* d_in, const int* in_sizes, int n_in,
                              void* d_out, int out_size) {
    const float* xi = (const float*)d_in[0];
    const float* S  = (const float*)d_in[1];
    const float* Tm = (const float*)d_in[2];
    const float* hh = (const float*)d_in[3];
    const float* W1 = (const float*)d_in[4];
    const float* b1 = (const float*)d_in[5];
    const float* W2 = (const float*)d_in[6];
    const float* b2 = (const float*)d_in[7];
    const float* W3 = (const float*)d_in[8];
    const float* b3 = (const float*)d_in[9];
    const float* W4 = (const float*)d_in[10];
    const float* b4 = (const float*)d_in[11];

    const size_t shb = (size_t)(LL + 5472) * sizeof(float2);  // ~171 KB
    cudaFuncSetAttribute(k_fft_in, cudaFuncAttributeMaxDynamicSharedMemorySize, (int)shb);
    cudaFuncSetAttribute(k_fft_xi, cudaFuncAttributeMaxDynamicSharedMemorySize, (int)shb);
    cudaFuncSetAttribute(k_inv,    cudaFuncAttributeMaxDynamicSharedMemorySize, (int)shb);

    k_twiddle<<<(TWF + 255) / 256, 256>>>();
    k_fft_in<<<102, NTH, shb>>>(S, Tm);
    k_fft_xi<<<64, NTH, shb>>>(xi);
    dim3 gi(NT, NB);
    k_inv<<<gi, NTH, shb>>>(hh);
    k_head<<<NB, 128>>>(W1, b1, W2, b2, W3, b3, W4, b4, (float*)d_out);
}

// round 5
// speedup vs baseline: 2.3101x; 1.1366x over previous
#include <cuda_runtime.h>
#include <cuda_fp16.h>
#include <math.h>

#define LL   16384
#define KTL  4096
#define NB   32
#define NT   50
#define NTH  512

// compact per-stage twiddle tables, flat layout
#define TWF   5461
#define O4096 0
#define O1024 4096
#define O256  5120
#define O64   5376
#define O16   5440
#define O4    5456
#define O1    5460

// ---------------- device scratch ----------------
__device__ float2  g_S[2][LL];        // S spectra (fp32, tiny)
__device__ __half2 g_H[100][LL];      // template spectra (fp16 complex)
__device__ __half2 g_D[64][LL];       // Xi*conj(S) spectra (fp16 complex)
__device__ float   g_z[NB * 2 * NT];
__device__ float2  g_twf[TWF];

// smem bank swizzle: pure permutation, applied to ALL workspace accesses
#define SW(k) ((k) ^ (((k) >> 4) & 15))

// ---------------- complex helpers ----------------
__device__ __forceinline__ float2 cadd(float2 a, float2 b) { return make_float2(a.x + b.x, a.y + b.y); }
__device__ __forceinline__ float2 csub(float2 a, float2 b) { return make_float2(a.x - b.x, a.y - b.y); }
__device__ __forceinline__ float2 cmul(float2 a, float2 b) {
    return make_float2(a.x * b.x - a.y * b.y, a.x * b.y + a.y * b.x);
}
__device__ __forceinline__ float2 cmulcj(float2 a, float2 b) {  // a * conj(b)
    return make_float2(a.x * b.x + a.y * b.y, a.y * b.x - a.x * b.y);
}

// load 4 consecutive fp16 complex values as float2 (one 16B LDG)
__device__ __forceinline__ void ld4h(const __half2* __restrict__ p, float2 v[4]) {
    uint4 u = *reinterpret_cast<const uint4*>(p);
    v[0] = __half22float2(*reinterpret_cast<__half2*>(&u.x));
    v[1] = __half22float2(*reinterpret_cast<__half2*>(&u.y));
    v[2] = __half22float2(*reinterpret_cast<__half2*>(&u.z));
    v[3] = __half22float2(*reinterpret_cast<__half2*>(&u.w));
}

// store 4 consecutive complex values as fp16 (one 16B STG)
__device__ __forceinline__ void st4h(__half2* __restrict__ p, float2 a, float2 b,
                                     float2 c, float2 d) {
    uint4 u;
    *reinterpret_cast<__half2*>(&u.x) = __floats2half2_rn(a.x, a.y);
    *reinterpret_cast<__half2*>(&u.y) = __floats2half2_rn(b.x, b.y);
    *reinterpret_cast<__half2*>(&u.z) = __floats2half2_rn(c.x, c.y);
    *reinterpret_cast<__half2*>(&u.w) = __floats2half2_rn(d.x, d.y);
    *reinterpret_cast<uint4*>(p) = u;
}

// forward DIF radix-4: butterfly then twiddle outputs (w = exp(-2pi i /4m))
__device__ __forceinline__ void bf_fwd(float2& x0, float2& x1, float2& x2, float2& x3, float2 w1) {
    float2 p02 = cadd(x0, x2), m02 = csub(x0, x2);
    float2 p13 = cadd(x1, x3), m13 = csub(x1, x3);
    float2 ni  = make_float2(m13.y, -m13.x);      // -i*(x1-x3)
    float2 b0 = cadd(p02, p13), b1 = cadd(m02, ni);
    float2 b2 = csub(p02, p13), b3 = csub(m02, ni);
    float2 w2 = make_float2(w1.x * w1.x - w1.y * w1.y, 2.f * w1.x * w1.y);
    float2 w3 = cmul(w2, w1);
    x0 = b0; x1 = cmul(b1, w1); x2 = cmul(b2, w2); x3 = cmul(b3, w3);
}

// inverse DIT radix-4: conj-twiddle inputs then butterfly
__device__ __forceinline__ void bf_inv(float2& x0, float2& x1, float2& x2, float2& x3, float2 w1) {
    w1.y = -w1.y;
    float2 w2 = make_float2(w1.x * w1.x - w1.y * w1.y, 2.f * w1.x * w1.y);
    float2 w3 = cmul(w2, w1);
    float2 a1 = cmul(x1, w1), a2 = cmul(x2, w2), a3 = cmul(x3, w3);
    float2 p02 = cadd(x0, a2), m02 = csub(x0, a2);
    float2 p13 = cadd(a1, a3), m13 = csub(a1, a3);
    float2 pi  = make_float2(-m13.y, m13.x);      // +i*(a1-a3)
    x0 = cadd(p02, p13); x1 = cadd(m02, pi);
    x2 = csub(p02, p13); x3 = csub(m02, pi);
}

// ---------------- twiddle generation (double precision) ----------------
__global__ void k_twiddle() {
    int i = blockIdx.x * blockDim.x + threadIdx.x;
    if (i >= TWF) return;
    int m, j;
    if      (i < O1024) { m = 4096; j = i; }
    else if (i < O256)  { m = 1024; j = i - O1024; }
    else if (i < O64)   { m = 256;  j = i - O256; }
    else if (i < O16)   { m = 64;   j = i - O64; }
    else if (i < O4)    { m = 16;   j = i - O16; }
    else if (i < O1)    { m = 4;    j = i - O4; }
    else                { m = 1;    j = 0; }
    double a = -2.0 * 3.14159265358979323846 * (double)j / (4.0 * (double)m);
    double s, c; sincos(a, &s, &c);
    g_twf[i] = make_float2((float)c, (float)s);
}

__device__ __forceinline__ void loadtw(float2* tw) {
    for (int k = threadIdx.x; k < TWF; k += NTH) tw[k] = g_twf[k];
}

// ---------------- combined radix-16 pass (two radix-4 stages in registers) ----------------
template <int MS, bool FWD>
__device__ void pass16(float2* __restrict__ s, const float2* __restrict__ Ts,
                       const float2* __restrict__ Tb) {
    const int tid = threadIdx.x;
#pragma unroll 1
    for (int i = 0; i < 2; i++) {
        const int tau  = tid + i * NTH;
        const int j    = tau & (MS - 1);
        const int g    = tau / MS;
        const int base = g * (16 * MS) + j;
        float2 x[16];
#pragma unroll
        for (int q = 0; q < 16; q++) x[q] = s[SW(base + q * MS)];
        if (FWD) {
#pragma unroll
            for (int q0 = 0; q0 < 4; q0++) {
                float2 wb = Tb[j + q0 * MS];
                bf_fwd(x[q0], x[q0 + 4], x[q0 + 8], x[q0 + 12], wb);
            }
            float2 ws = Ts[j];
#pragma unroll
            for (int q1 = 0; q1 < 4; q1++)
                bf_fwd(x[4 * q1], x[4 * q1 + 1], x[4 * q1 + 2], x[4 * q1 + 3], ws);
        } else {
            float2 ws = Ts[j];
#pragma unroll
            for (int q1 = 0; q1 < 4; q1++)
                bf_inv(x[4 * q1], x[4 * q1 + 1], x[4 * q1 + 2], x[4 * q1 + 3], ws);
#pragma unroll
            for (int q0 = 0; q0 < 4; q0++) {
                float2 wb = Tb[j + q0 * MS];
                bf_inv(x[q0], x[q0 + 4], x[q0 + 8], x[q0 + 12], wb);
            }
        }
#pragma unroll
        for (int q = 0; q < 16; q++) s[SW(base + q * MS)] = x[q];
    }
    __syncthreads();
}

// forward stages (4096,1024),(256,64),(16,4); final m=1 is fused by callers
__device__ __forceinline__ void fwd_core(float2* dat, const float2* tw) {
    pass16<1024, true>(dat, tw + O1024, tw + O4096);
    pass16<64,   true>(dat, tw + O64,   tw + O256);
    pass16<4,    true>(dat, tw + O4,    tw + O16);
}

// final forward m=1 butterfly (twiddle = 1), inputs from swizzled smem
__device__ __forceinline__ void last_fwd(const float2* dat, int k0, float2& b0, float2& b1,
                                         float2& b2, float2& b3) {
    float2 x0 = dat[SW(k0)], x1 = dat[SW(k0 + 1)], x2 = dat[SW(k0 + 2)], x3 = dat[SW(k0 + 3)];
    float2 p02 = cadd(x0, x2), m02 = csub(x0, x2);
    float2 p13 = cadd(x1, x3), m13 = csub(x1, x3);
    float2 ni  = make_float2(m13.y, -m13.x);
    b0 = cadd(p02, p13); b1 = cadd(m02, ni);
    b2 = csub(p02, p13); b3 = csub(m02, ni);
}

// ---------------- forward FFT of S (2) + templates (100) ----------------
__global__ void __launch_bounds__(NTH, 1) k_fft_in(const float* __restrict__ Sm,
                                                   const float* __restrict__ Tm) {
    extern __shared__ float2 sm[];
    float2* dat = sm;
    float2* tw  = sm + LL;
    const int tid = threadIdx.x, bi = blockIdx.x;
    loadtw(tw);
    if (bi < 2) {
        const float* src = Sm + bi * LL;
        for (int t = tid; t < LL; t += NTH) dat[SW(t)] = make_float2(src[t], 0.f);
    } else {
        const float* src = Tm + (size_t)(bi - 2) * KTL;
        for (int t = tid; t < LL; t += NTH)
            dat[SW(t)] = make_float2(t < KTL ? src[t] : 0.f, 0.f);
    }
    __syncthreads();
    fwd_core(dat, tw);
    if (bi < 2) {
        float2* out = g_S[bi];
#pragma unroll 1
        for (int i = 0; i < 8; i++) {
            const int k0 = 4 * (tid + i * NTH);
            float2 b0, b1, b2, b3;
            last_fwd(dat, k0, b0, b1, b2, b3);
            float4* o4 = (float4*)(out + k0);
            o4[0] = make_float4(b0.x, b0.y, b1.x, b1.y);
            o4[1] = make_float4(b2.x, b2.y, b3.x, b3.y);
        }
    } else {
        __half2* out = g_H[bi - 2];
#pragma unroll 1
        for (int i = 0; i < 8; i++) {
            const int k0 = 4 * (tid + i * NTH);
            float2 b0, b1, b2, b3;
            last_fwd(dat, k0, b0, b1, b2, b3);
            st4h(out + k0, b0, b1, b2, b3);
        }
    }
}

// ---------------- forward FFT of xi (64), fused D = Xi * conj(S) ----------------
__global__ void __launch_bounds__(NTH, 1) k_fft_xi(const float* __restrict__ xi) {
    extern __shared__ float2 sm[];
    float2* dat = sm;
    float2* tw  = sm + LL;
    const int tid = threadIdx.x, bi = blockIdx.x;  // b*2 + c
    const int c   = bi & 1;
    loadtw(tw);
    const float* src = xi + (size_t)bi * LL;
    for (int t = tid; t < LL; t += NTH) dat[SW(t)] = make_float2(src[t], 0.f);
    __syncthreads();
    fwd_core(dat, tw);
    const float2* Sc = g_S[c];
    __half2* Dd = g_D[bi];
#pragma unroll 1
    for (int i = 0; i < 8; i++) {
        const int k0 = 4 * (tid + i * NTH);
        float2 b0, b1, b2, b3;
        last_fwd(dat, k0, b0, b1, b2, b3);
        const float4* s4 = (const float4*)(Sc + k0);
        float4 sA = s4[0], sB = s4[1];
        float2 d0 = cmulcj(b0, make_float2(sA.x, sA.y));
        float2 d1 = cmulcj(b1, make_float2(sA.z, sA.w));
        float2 d2 = cmulcj(b2, make_float2(sB.x, sB.y));
        float2 d3 = cmulcj(b3, make_float2(sB.z, sB.w));
        st4h(Dd + k0, d0, d1, d2, d3);
    }
}

// ---------------- inverse: pointwise+stage(m=1) -> (4,16) -> (64,256) -> (1024,4096)+max ----------------
__global__ void __launch_bounds__(NTH, 1) k_inv(const float* __restrict__ hh) {
    extern __shared__ float2 sm[];
    float2* dat = sm;
    float2* tw  = sm + LL;
    const int tid = threadIdx.x;
    const int n = blockIdx.x, b = blockIdx.y;
    loadtw(tw);
    const __half2* __restrict__ D0 = g_D[b * 2 + 0];
    const __half2* __restrict__ D1 = g_D[b * 2 + 1];
    const __half2* __restrict__ H0 = g_H[n * 2 + 0];
    const __half2* __restrict__ H1 = g_H[n * 2 + 1];
    // pointwise spectral product (pack channels: GA + i*GE) fused with first
    // inverse stage (m=1, twiddle=1); one 16B load per stream per 4 bins.
#pragma unroll 1
    for (int i = 0; i < 8; i++) {
        const int tau = tid + i * NTH;
        const int k0  = 4 * tau;
        float2 d[4], e[4], h[4], f[4];
        ld4h(D0 + k0, d);
        ld4h(D1 + k0, e);
        ld4h(H0 + k0, h);
        ld4h(H1 + k0, f);
        float2 v[4];
#pragma unroll
        for (int q = 0; q < 4; q++) {
            float2 GA = cmulcj(d[q], h[q]);
            float2 GE = cmulcj(e[q], f[q]);
            v[q] = make_float2(GA.x - GE.y, GA.y + GE.x);
        }
        // inverse radix-4, m=1, w=1
        float2 p02 = cadd(v[0], v[2]), m02 = csub(v[0], v[2]);
        float2 p13 = cadd(v[1], v[3]), m13 = csub(v[1], v[3]);
        float2 pi  = make_float2(-m13.y, m13.x);
        dat[SW(k0)]     = cadd(p02, p13);
        dat[SW(k0 + 1)] = cadd(m02, pi);
        dat[SW(k0 + 2)] = csub(p02, p13);
        dat[SW(k0 + 3)] = csub(m02, pi);
    }
    __syncthreads();
    pass16<4,  false>(dat, tw + O4,  tw + O16);
    pass16<64, false>(dat, tw + O64, tw + O256);
    // last combined pass (1024,4096): results stay in registers, fold max
    float mA = -3.4e38f, mE = -3.4e38f;
#pragma unroll 1
    for (int i = 0; i < 2; i++) {
        const int j = tid + i * NTH;  // g = 0 for all tiles here
        float2 x[16];
#pragma unroll
        for (int q = 0; q < 16; q++) x[q] = dat[SW(j + q * 1024)];
        float2 ws = tw[O1024 + j];
#pragma unroll
        for (int q1 = 0; q1 < 4; q1++)
            bf_inv(x[4 * q1], x[4 * q1 + 1], x[4 * q1 + 2], x[4 * q1 + 3], ws);
#pragma unroll
        for (int q0 = 0; q0 < 4; q0++) {
            float2 wb = tw[O4096 + j + q0 * 1024];
            bf_inv(x[q0], x[q0 + 4], x[q0 + 8], x[q0 + 12], wb);
        }
#pragma unroll
        for (int q = 0; q < 16; q++) {
            mA = fmaxf(mA, x[q].x);
            mE = fmaxf(mE, x[q].y);
        }
    }
#pragma unroll
    for (int o = 16; o > 0; o >>= 1) {
        mA = fmaxf(mA, __shfl_xor_sync(0xffffffffu, mA, o));
        mE = fmaxf(mE, __shfl_xor_sync(0xffffffffu, mE, o));
    }
    __shared__ float rA[NTH / 32], rE[NTH / 32];
    if ((tid & 31) == 0) { rA[tid >> 5] = mA; rE[tid >> 5] = mE; }
    __syncthreads();
    if (tid == 0) {
        for (int i = 1; i < NTH / 32; i++) { mA = fmaxf(mA, rA[i]); mE = fmaxf(mE, rE[i]); }
        const float sc = 1.f / (float)LL;
        g_z[(b * 2 + 0) * NT + n] = mA * sc / hh[n * 2 + 0];
        g_z[(b * 2 + 1) * NT + n] = mE * sc / hh[n * 2 + 1];
    }
}

// ---------------- tiny CNN + MLP head ----------------
__device__ __forceinline__ float sigm(float x) { return 1.f / (1.f + __expf(-x)); }

__global__ void k_head(const float* __restrict__ W1, const float* __restrict__ b1,
                       const float* __restrict__ W2, const float* __restrict__ b2,
                       const float* __restrict__ W3, const float* __restrict__ b3,
                       const float* __restrict__ W4, const float* __restrict__ b4,
                       float* __restrict__ out) {
    __shared__ float zb[2][NT];
    __shared__ float p1[16][16];
    __shared__ float p2[32][4];
    __shared__ float h1[32];
    const int b = blockIdx.x, tid = threadIdx.x;
    for (int i = tid; i < 2 * NT; i += blockDim.x) zb[i / NT][i % NT] = g_z[b * 2 * NT + i];
    __syncthreads();
    for (int i = tid; i < 16 * 16; i += blockDim.x) {
        int o = i >> 4, tp = i & 15;
        float mx = -3.4e38f;
        for (int q = 0; q < 3; q++) {
            int t = 3 * tp + q;
            float acc = b1[o];
            for (int c = 0; c < 2; c++)
                for (int j = 0; j < 3; j++) acc += zb[c][t + j] * W1[(o * 2 + c) * 3 + j];
            mx = fmaxf(mx, sigm(acc));
        }
        p1[o][tp] = mx;
    }
    __syncthreads();
    for (int i = tid; i < 32 * 4; i += blockDim.x) {
        int o = i >> 2, tp = i & 3;
        float mx = -3.4e38f;
        for (int q = 0; q < 3; q++) {
            int t = 3 * tp + q;
            float acc = b2[o];
            for (int ci = 0; ci < 16; ci++)
                for (int j = 0; j < 3; j++) acc += p1[ci][t + j] * W2[(o * 16 + ci) * 3 + j];
            mx = fmaxf(mx, sigm(acc));
        }
        p2[o][tp] = mx;
    }
    __syncthreads();
    if (tid < 32) {
        float acc = b3[tid];
        for (int i = 0; i < 128; i++) acc += p2[i >> 2][i & 3] * W3[tid * 128 + i];
        h1[tid] = fmaxf(acc, 0.f);
    }
    __syncthreads();
    if (tid < 2) {
        float acc = b4[tid];
        for (int i = 0; i < 32; i++) acc += h1[i] * W4[tid * 32 + i];
        out[b * 2 + tid] = acc;
    }
}

// ---------------- launch ----------------
extern "C" void kernel_launch(void* const* d_in, const int* in_sizes, int n_in,
                              void* d_out, int out_size) {
    const float* xi = (const float*)d_in[0];
    const float* S  = (const float*)d_in[1];
    const float* Tm = (const float*)d_in[2];
    const float* hh = (const float*)d_in[3];
    const float* W1 = (const float*)d_in[4];
    const float* b1 = (const float*)d_in[5];
    const float* W2 = (const float*)d_in[6];
    const float* b2 = (const float*)d_in[7];
    const float* W3 = (const float*)d_in[8];
    const float* b3 = (const float*)d_in[9];
    const float* W4 = (const float*)d_in[10];
    const float* b4 = (const float*)d_in[11];

    const size_t shb = (size_t)(LL + 5472) * sizeof(float2);  // ~171 KB
    cudaFuncSetAttribute(k_fft_in, cudaFuncAttributeMaxDynamicSharedMemorySize, (int)shb);
    cudaFuncSetAttribute(k_fft_xi, cudaFuncAttributeMaxDynamicSharedMemorySize, (int)shb);
    cudaFuncSetAttribute(k_inv,    cudaFuncAttributeMaxDynamicSharedMemorySize, (int)shb);

    k_twiddle<<<(TWF + 255) / 256, 256>>>();
    k_fft_in<<<102, NTH, shb>>>(S, Tm);
    k_fft_xi<<<64, NTH, shb>>>(xi);
    dim3 gi(NT, NB);
    k_inv<<<gi, NTH, shb>>>(hh);
    k_head<<<NB, 128>>>(W1, b1, W2, b2, W3, b3, W4, b4, (float*)d_out);
}

// round 7
// speedup vs baseline: 2.8269x; 1.2237x over previous
#include <cuda_runtime.h>
#include <cuda_fp16.h>
#include <math.h>

#define LL   16384
#define KTL  4096
#define NB   32
#define NT   50
#define NTH  512

// compact twiddle tables (identity: tw_big[j+q0*MS] = tw_base[j]*C[q0])
#define T1024S 0
#define T1024B 1024
#define T64S   2048
#define T64B   2112
#define T4S    2176
#define T4B    2180
#define TWTOT  2184

// ---------------- device scratch ----------------
__device__ float2  g_S[2][LL];        // S spectra (fp32)
__device__ __half2 g_H[100][LL];      // template spectra (fp16 complex)
__device__ __half2 g_D[64][LL];       // Xi*conj(S) spectra (fp16 complex)
__device__ float   g_z[NB * 2 * NT];
__device__ float2  g_twf[TWTOT];

// swizzle for fp32 (8B) workspace — forward kernels
#define SW(k)  ((k) ^ (((k) >> 4) & 15))
// swizzle for fp16 (4B) workspace — inverse kernel (conflict-free for
// strides 1,4,64,1024; preserves low 2 bits => 16B vector stores OK)
#define SWH(k) ((k) ^ ((((k) >> 6) & 7) << 2))

// ---------------- complex helpers ----------------
__device__ __forceinline__ float2 cadd(float2 a, float2 b) { return make_float2(a.x + b.x, a.y + b.y); }
__device__ __forceinline__ float2 csub(float2 a, float2 b) { return make_float2(a.x - b.x, a.y - b.y); }
__device__ __forceinline__ float2 cmul(float2 a, float2 b) {
    return make_float2(a.x * b.x - a.y * b.y, a.x * b.y + a.y * b.x);
}
__device__ __forceinline__ float2 cmulcj(float2 a, float2 b) {  // a * conj(b)
    return make_float2(a.x * b.x + a.y * b.y, a.y * b.x - a.x * b.y);
}

// C[q0] = exp(-2*pi*i*q0/16)
__device__ __forceinline__ float2 c16(int q0) {
    if (q0 == 1) return make_float2(0.9238795325112867f, -0.3826834323650898f);
    if (q0 == 2) return make_float2(0.7071067811865476f, -0.7071067811865476f);
    return make_float2(0.3826834323650898f, -0.9238795325112867f);
}

// load 4 consecutive fp16 complex values as float2 (one 16B LDG)
__device__ __forceinline__ void ld4h(const __half2* __restrict__ p, float2 v[4]) {
    uint4 u = *reinterpret_cast<const uint4*>(p);
    v[0] = __half22float2(*reinterpret_cast<__half2*>(&u.x));
    v[1] = __half22float2(*reinterpret_cast<__half2*>(&u.y));
    v[2] = __half22float2(*reinterpret_cast<__half2*>(&u.z));
    v[3] = __half22float2(*reinterpret_cast<__half2*>(&u.w));
}

__device__ __forceinline__ void st4h(__half2* __restrict__ p, float2 a, float2 b,
                                     float2 c, float2 d) {
    uint4 u;
    *reinterpret_cast<__half2*>(&u.x) = __floats2half2_rn(a.x, a.y);
    *reinterpret_cast<__half2*>(&u.y) = __floats2half2_rn(b.x, b.y);
    *reinterpret_cast<__half2*>(&u.z) = __floats2half2_rn(c.x, c.y);
    *reinterpret_cast<__half2*>(&u.w) = __floats2half2_rn(d.x, d.y);
    *reinterpret_cast<uint4*>(p) = u;
}

// forward DIF radix-4: butterfly then twiddle outputs
__device__ __forceinline__ void bf_fwd(float2& x0, float2& x1, float2& x2, float2& x3, float2 w1) {
    float2 p02 = cadd(x0, x2), m02 = csub(x0, x2);
    float2 p13 = cadd(x1, x3), m13 = csub(x1, x3);
    float2 ni  = make_float2(m13.y, -m13.x);
    float2 b0 = cadd(p02, p13), b1 = cadd(m02, ni);
    float2 b2 = csub(p02, p13), b3 = csub(m02, ni);
    float2 w2 = make_float2(w1.x * w1.x - w1.y * w1.y, 2.f * w1.x * w1.y);
    float2 w3 = cmul(w2, w1);
    x0 = b0; x1 = cmul(b1, w1); x2 = cmul(b2, w2); x3 = cmul(b3, w3);
}

// inverse DIT radix-4: conj-twiddle inputs then butterfly
__device__ __forceinline__ void bf_inv(float2& x0, float2& x1, float2& x2, float2& x3, float2 w1) {
    w1.y = -w1.y;
    float2 w2 = make_float2(w1.x * w1.x - w1.y * w1.y, 2.f * w1.x * w1.y);
    float2 w3 = cmul(w2, w1);
    float2 a1 = cmul(x1, w1), a2 = cmul(x2, w2), a3 = cmul(x3, w3);
    float2 p02 = cadd(x0, a2), m02 = csub(x0, a2);
    float2 p13 = cadd(a1, a3), m13 = csub(a1, a3);
    float2 pi  = make_float2(-m13.y, m13.x);
    x0 = cadd(p02, p13); x1 = cadd(m02, pi);
    x2 = csub(p02, p13); x3 = csub(m02, pi);
}

// ---------------- twiddle generation (double precision) ----------------
__global__ void k_twiddle() {
    int i = blockIdx.x * blockDim.x + threadIdx.x;
    if (i >= TWTOT) return;
    int j; double den;
    if      (i < T1024B) { j = i;          den = 4096.0;  }
    else if (i < T64S)   { j = i - T1024B; den = 16384.0; }
    else if (i < T64B)   { j = i - T64S;   den = 256.0;   }
    else if (i < T4S)    { j = i - T64B;   den = 1024.0;  }
    else if (i < T4B)    { j = i - T4S;    den = 16.0;    }
    else                 { j = i - T4B;    den = 64.0;    }
    double a = -2.0 * 3.14159265358979323846 * (double)j / den;
    double s, c; sincos(a, &s, &c);
    g_twf[i] = make_float2((float)c, (float)s);
}

__device__ __forceinline__ void loadtw(float2* tw) {
    for (int k = threadIdx.x; k < TWTOT; k += NTH) tw[k] = g_twf[k];
}

// ---------------- forward radix-16 pass, fp32 workspace ----------------
template <int MS, int TSOF, int TBOF>
__device__ void pass16f(float2* __restrict__ s, const float2* __restrict__ tw) {
    const int tid = threadIdx.x;
#pragma unroll 1
    for (int i = 0; i < 2; i++) {
        const int tau  = tid + i * NTH;
        const int j    = tau & (MS - 1);
        const int g    = tau / MS;
        const int base = g * (16 * MS) + j;
        float2 x[16];
#pragma unroll
        for (int q = 0; q < 16; q++) x[q] = s[SW(base + q * MS)];
        float2 tb = tw[TBOF + j];
        bf_fwd(x[0], x[4], x[8], x[12], tb);
#pragma unroll
        for (int q0 = 1; q0 < 4; q0++) {
            float2 wb = cmul(tb, c16(q0));
            bf_fwd(x[q0], x[q0 + 4], x[q0 + 8], x[q0 + 12], wb);
        }
        float2 ws = tw[TSOF + j];
#pragma unroll
        for (int q1 = 0; q1 < 4; q1++)
            bf_fwd(x[4 * q1], x[4 * q1 + 1], x[4 * q1 + 2], x[4 * q1 + 3], ws);
#pragma unroll
        for (int q = 0; q < 16; q++) s[SW(base + q * MS)] = x[q];
    }
    __syncthreads();
}

__device__ __forceinline__ void fwd_core(float2* dat, const float2* tw) {
    pass16f<1024, T1024S, T1024B>(dat, tw);
    pass16f<64,   T64S,   T64B>(dat, tw);
    pass16f<4,    T4S,    T4B>(dat, tw);
}

// final forward m=1 butterfly (twiddle = 1)
__device__ __forceinline__ void last_fwd(const float2* dat, int k0, float2& b0, float2& b1,
                                         float2& b2, float2& b3) {
    float2 x0 = dat[SW(k0)], x1 = dat[SW(k0 + 1)], x2 = dat[SW(k0 + 2)], x3 = dat[SW(k0 + 3)];
    float2 p02 = cadd(x0, x2), m02 = csub(x0, x2);
    float2 p13 = cadd(x1, x3), m13 = csub(x1, x3);
    float2 ni  = make_float2(m13.y, -m13.x);
    b0 = cadd(p02, p13); b1 = cadd(m02, ni);
    b2 = csub(p02, p13); b3 = csub(m02, ni);
}

// ---------------- inverse radix-16 pass, fp16 workspace ----------------
template <int MS, int TSOF, int TBOF>
__device__ void pass16h(__half2* __restrict__ s, const float2* __restrict__ tw) {
    const int tid = threadIdx.x;
#pragma unroll 1
    for (int i = 0; i < 2; i++) {
        const int tau  = tid + i * NTH;
        const int j    = tau & (MS - 1);
        const int g    = tau / MS;
        const int base = g * (16 * MS) + j;
        float2 x[16];
#pragma unroll
        for (int q = 0; q < 16; q++) x[q] = __half22float2(s[SWH(base + q * MS)]);
        float2 ws = tw[TSOF + j];
#pragma unroll
        for (int q1 = 0; q1 < 4; q1++)
            bf_inv(x[4 * q1], x[4 * q1 + 1], x[4 * q1 + 2], x[4 * q1 + 3], ws);
        float2 tb = tw[TBOF + j];
        bf_inv(x[0], x[4], x[8], x[12], tb);
#pragma unroll
        for (int q0 = 1; q0 < 4; q0++) {
            float2 wb = cmul(tb, c16(q0));
            bf_inv(x[q0], x[q0 + 4], x[q0 + 8], x[q0 + 12], wb);
        }
#pragma unroll
        for (int q = 0; q < 16; q++)
            s[SWH(base + q * MS)] = __floats2half2_rn(x[q].x, x[q].y);
    }
    __syncthreads();
}

// ---------------- forward FFT of S (2) + templates (100) ----------------
__global__ void __launch_bounds__(NTH, 1) k_fft_in(const float* __restrict__ Sm,
                                                   const float* __restrict__ Tm) {
    extern __shared__ float2 sm[];
    float2* dat = sm;
    float2* tw  = sm + LL;
    const int tid = threadIdx.x, bi = blockIdx.x;
    loadtw(tw);
    if (bi < 2) {
        const float* src = Sm + bi * LL;
        for (int t = tid; t < LL; t += NTH) dat[SW(t)] = make_float2(src[t], 0.f);
    } else {
        const float* src = Tm + (size_t)(bi - 2) * KTL;
        for (int t = tid; t < LL; t += NTH)
            dat[SW(t)] = make_float2(t < KTL ? src[t] : 0.f, 0.f);
    }
    __syncthreads();
    fwd_core(dat, tw);
    if (bi < 2) {
        float2* out = g_S[bi];
#pragma unroll 1
        for (int i = 0; i < 8; i++) {
            const int k0 = 4 * (tid + i * NTH);
            float2 b0, b1, b2, b3;
            last_fwd(dat, k0, b0, b1, b2, b3);
            float4* o4 = (float4*)(out + k0);
            o4[0] = make_float4(b0.x, b0.y, b1.x, b1.y);
            o4[1] = make_float4(b2.x, b2.y, b3.x, b3.y);
        }
    } else {
        __half2* out = g_H[bi - 2];
#pragma unroll 1
        for (int i = 0; i < 8; i++) {
            const int k0 = 4 * (tid + i * NTH);
            float2 b0, b1, b2, b3;
            last_fwd(dat, k0, b0, b1, b2, b3);
            st4h(out + k0, b0, b1, b2, b3);
        }
    }
}

// ---------------- forward FFT of xi (64), fused D = Xi * conj(S) ----------------
__global__ void __launch_bounds__(NTH, 1) k_fft_xi(const float* __restrict__ xi) {
    extern __shared__ float2 sm[];
    float2* dat = sm;
    float2* tw  = sm + LL;
    const int tid = threadIdx.x, bi = blockIdx.x;  // b*2 + c
    const int c   = bi & 1;
    loadtw(tw);
    const float* src = xi + (size_t)bi * LL;
    for (int t = tid; t < LL; t += NTH) dat[SW(t)] = make_float2(src[t], 0.f);
    __syncthreads();
    fwd_core(dat, tw);
    const float2* Sc = g_S[c];
    __half2* Dd = g_D[bi];
#pragma unroll 1
    for (int i = 0; i < 8; i++) {
        const int k0 = 4 * (tid + i * NTH);
        float2 b0, b1, b2, b3;
        last_fwd(dat, k0, b0, b1, b2, b3);
        const float4* s4 = (const float4*)(Sc + k0);
        float4 sA = s4[0], sB = s4[1];
        float2 d0 = cmulcj(b0, make_float2(sA.x, sA.y));
        float2 d1 = cmulcj(b1, make_float2(sA.z, sA.w));
        float2 d2 = cmulcj(b2, make_float2(sB.x, sB.y));
        float2 d3 = cmulcj(b3, make_float2(sB.z, sB.w));
        st4h(Dd + k0, d0, d1, d2, d3);
    }
}

// ---------------- inverse: 2 blocks/SM, fp16 workspace ----------------
__global__ void __launch_bounds__(NTH, 2) k_inv(const float* __restrict__ hh) {
    extern __shared__ char smraw[];
    __half2* dat = (__half2*)smraw;                     // 64 KB
    float2*  tw  = (float2*)(smraw + (size_t)LL * 4);  // 17.1 KB
    const int tid = threadIdx.x;
    const int n = blockIdx.x, b = blockIdx.y;
    loadtw(tw);
    const __half2* __restrict__ D0 = g_D[b * 2 + 0];
    const __half2* __restrict__ D1 = g_D[b * 2 + 1];
    const __half2* __restrict__ H0 = g_H[n * 2 + 0];
    const __half2* __restrict__ H1 = g_H[n * 2 + 1];
    // pointwise spectral product (pack: GA + i*GE) fused with inverse m=1 stage
#pragma unroll 1
    for (int i = 0; i < 8; i++) {
        const int k0 = 4 * (tid + i * NTH);
        float2 d[4], e[4], h[4], f[4];
        ld4h(D0 + k0, d);
        ld4h(D1 + k0, e);
        ld4h(H0 + k0, h);
        ld4h(H1 + k0, f);
        float2 v[4];
#pragma unroll
        for (int q = 0; q < 4; q++) {
            float2 GA = cmulcj(d[q], h[q]);
            float2 GE = cmulcj(e[q], f[q]);
            v[q] = make_float2(GA.x - GE.y, GA.y + GE.x);
        }
        float2 p02 = cadd(v[0], v[2]), m02 = csub(v[0], v[2]);
        float2 p13 = cadd(v[1], v[3]), m13 = csub(v[1], v[3]);
        float2 pi  = make_float2(-m13.y, m13.x);
        st4h(dat + SWH(k0), cadd(p02, p13), cadd(m02, pi),
             csub(p02, p13), csub(m02, pi));
    }
    __syncthreads();
    pass16h<4,  T4S,  T4B>(dat, tw);
    pass16h<64, T64S, T64B>(dat, tw);
    // last pass (1024,4096) in registers, fold max
    float mA = -3.4e38f, mE = -3.4e38f;
#pragma unroll 1
    for (int i = 0; i < 2; i++) {
        const int j = tid + i * NTH;
        float2 x[16];
#pragma unroll
        for (int q = 0; q < 16; q++) x[q] = __half22float2(dat[SWH(j + q * 1024)]);
        float2 ws = tw[T1024S + j];
#pragma unroll
        for (int q1 = 0; q1 < 4; q1++)
            bf_inv(x[4 * q1], x[4 * q1 + 1], x[4 * q1 + 2], x[4 * q1 + 3], ws);
        float2 tb = tw[T1024B + j];
        bf_inv(x[0], x[4], x[8], x[12], tb);
#pragma unroll
        for (int q0 = 1; q0 < 4; q0++) {
            float2 wb = cmul(tb, c16(q0));
            bf_inv(x[q0], x[q0 + 4], x[q0 + 8], x[q0 + 12], wb);
        }
#pragma unroll
        for (int q = 0; q < 16; q++) {
            mA = fmaxf(mA, x[q].x);
            mE = fmaxf(mE, x[q].y);
        }
    }
#pragma unroll
    for (int o = 16; o > 0; o >>= 1) {
        mA = fmaxf(mA, __shfl_xor_sync(0xffffffffu, mA, o));
        mE = fmaxf(mE, __shfl_xor_sync(0xffffffffu, mE, o));
    }
    __shared__ float rA[NTH / 32], rE[NTH / 32];
    if ((tid & 31) == 0) { rA[tid >> 5] = mA; rE[tid >> 5] = mE; }
    __syncthreads();
    if (tid == 0) {
        for (int i = 1; i < NTH / 32; i++) { mA = fmaxf(mA, rA[i]); mE = fmaxf(mE, rE[i]); }
        const float sc = 1.f / (float)LL;
        g_z[(b * 2 + 0) * NT + n] = mA * sc / hh[n * 2 + 0];
        g_z[(b * 2 + 1) * NT + n] = mE * sc / hh[n * 2 + 1];
    }
}

// ---------------- tiny CNN + MLP head ----------------
__device__ __forceinline__ float sigm(float x) { return 1.f / (1.f + __expf(-x)); }

__global__ void k_head(const float* __restrict__ W1, const float* __restrict__ b1,
                       const float* __restrict__ W2, const float* __restrict__ b2,
                       const float* __restrict__ W3, const float* __restrict__ b3,
                       const float* __restrict__ W4, const float* __restrict__ b4,
                       float* __restrict__ out) {
    __shared__ float zb[2][NT];
    __shared__ float p1[16][16];
    __shared__ float p2[32][4];
    __shared__ float h1[32];
    const int b = blockIdx.x, tid = threadIdx.x;
    for (int i = tid; i < 2 * NT; i += blockDim.x) zb[i / NT][i % NT] = g_z[b * 2 * NT + i];
    __syncthreads();
    for (int i = tid; i < 16 * 16; i += blockDim.x) {
        int o = i >> 4, tp = i & 15;
        float mx = -3.4e38f;
        for (int q = 0; q < 3; q++) {
            int t = 3 * tp + q;
            float acc = b1[o];
            for (int c = 0; c < 2; c++)
                for (int j = 0; j < 3; j++) acc += zb[c][t + j] * W1[(o * 2 + c) * 3 + j];
            mx = fmaxf(mx, sigm(acc));
        }
        p1[o][tp] = mx;
    }
    __syncthreads();
    for (int i = tid; i < 32 * 4; i += blockDim.x) {
        int o = i >> 2, tp = i & 3;
        float mx = -3.4e38f;
        for (int q = 0; q < 3; q++) {
            int t = 3 * tp + q;
            float acc = b2[o];
            for (int ci = 0; ci < 16; ci++)
                for (int j = 0; j < 3; j++) acc += p1[ci][t + j] * W2[(o * 16 + ci) * 3 + j];
            mx = fmaxf(mx, sigm(acc));
        }
        p2[o][tp] = mx;
    }
    __syncthreads();
    if (tid < 32) {
        float acc = b3[tid];
        for (int i = 0; i < 128; i++) acc += p2[i >> 2][i & 3] * W3[tid * 128 + i];
        h1[tid] = fmaxf(acc, 0.f);
    }
    __syncthreads();
    if (tid < 2) {
        float acc = b4[tid];
        for (int i = 0; i < 32; i++) acc += h1[i] * W4[tid * 32 + i];
        out[b * 2 + tid] = acc;
    }
}

// ---------------- launch ----------------
extern "C" void kernel_launch(void* const* d_in, const int* in_sizes, int n_in,
                              void* d_out, int out_size) {
    const float* xi = (const float*)d_in[0];
    const float* S  = (const float*)d_in[1];
    const float* Tm = (const float*)d_in[2];
    const float* hh = (const float*)d_in[3];
    const float* W1 = (const float*)d_in[4];
    const float* b1 = (const float*)d_in[5];
    const float* W2 = (const float*)d_in[6];
    const float* b2 = (const float*)d_in[7];
    const float* W3 = (const float*)d_in[8];
    const float* b3 = (const float*)d_in[9];
    const float* W4 = (const float*)d_in[10];
    const float* b4 = (const float*)d_in[11];

    const size_t shf = (size_t)(LL + TWTOT) * sizeof(float2);       // ~145 KB (forward)
    const size_t shi = (size_t)LL * 4 + (size_t)TWTOT * sizeof(float2);  // ~81 KB (inverse)
    cudaFuncSetAttribute(k_fft_in, cudaFuncAttributeMaxDynamicSharedMemorySize, (int)shf);
    cudaFuncSetAttribute(k_fft_xi, cudaFuncAttributeMaxDynamicSharedMemorySize, (int)shf);
    cudaFuncSetAttribute(k_inv,    cudaFuncAttributeMaxDynamicSharedMemorySize, (int)shi);

    k_twiddle<<<(TWTOT + 255) / 256, 256>>>();
    k_fft_in<<<102, NTH, shf>>>(S, Tm);
    k_fft_xi<<<64, NTH, shf>>>(xi);
    dim3 gi(NT, NB);
    k_inv<<<gi, NTH, shi>>>(hh);
    k_head<<<NB, 128>>>(W1, b1, W2, b2, W3, b3, W4, b4, (float*)d_out);
}